// round 7
// baseline (speedup 1.0000x reference)
#include <cuda_runtime.h>
#include <stdint.h>

// Problem constants (from reference): x [N, C, H, W] fp32
#define N_S   16
#define C_CH  128
#define HW    16384           // 128*128
#define HW4   4096            // HW / 4
#define K_TOP 1638            // max(int(0.1 * 16384), 1)

// Scratch (no allocations allowed in kernel_launch)
__device__ float d_stats[N_S * HW];   // per-(n, p) channel-sum
__device__ float d_scale[N_S * HW];   // per-(n, p) final multiplier

// ---------------------------------------------------------------------------
// Kernel A: channel-sum per spatial column. One thread per float4 group of p.
// Coalesced: consecutive threads -> consecutive 16B within a channel plane.
// ---------------------------------------------------------------------------
__global__ void stats_kernel(const float* __restrict__ x) {
    int t  = blockIdx.x * blockDim.x + threadIdx.x;   // [0, N_S*HW4)
    int n  = t >> 12;                                  // / HW4
    int p4 = t & (HW4 - 1);

    const float4* xp = reinterpret_cast<const float4*>(x) + (size_t)n * C_CH * HW4 + p4;

    float4 s0 = make_float4(0.f, 0.f, 0.f, 0.f);
    float4 s1 = make_float4(0.f, 0.f, 0.f, 0.f);
    #pragma unroll 8
    for (int c = 0; c < C_CH; c += 2) {
        float4 a = xp[(size_t)c * HW4];
        float4 b = xp[(size_t)(c + 1) * HW4];
        s0.x += a.x; s0.y += a.y; s0.z += a.z; s0.w += a.w;
        s1.x += b.x; s1.y += b.y; s1.z += b.z; s1.w += b.w;
    }
    float4 s;
    s.x = s0.x + s1.x; s.y = s0.y + s1.y; s.z = s0.z + s1.z; s.w = s0.w + s1.w;
    reinterpret_cast<float4*>(d_stats)[(n << 12) + p4] = s;
}

// ---------------------------------------------------------------------------
// Kernel B: per-sample exact top-k threshold via MSB-first radix select on
// sortable uint keys; stable (lowest-index-first) tie handling; writes the
// fused blend factor  mask*tau + (1 - tau)  per spatial position.
// One block per sample, 1024 threads.
// ---------------------------------------------------------------------------
__device__ __forceinline__ unsigned f2key(float f) {
    unsigned u = __float_as_uint(f);
    // monotonic map: larger float -> larger uint
    return u ^ ((unsigned)((int)u >> 31) | 0x80000000u);
}

__global__ void select_kernel(const float* __restrict__ tau_p) {
    const int n   = blockIdx.x;
    const int tid = threadIdx.x;
    const float* st = d_stats + n * HW;

    __shared__ unsigned hist[256];
    __shared__ unsigned s_prefix, s_remaining;
    __shared__ unsigned scnt[1024];

    if (tid == 0) { s_prefix = 0u; s_remaining = K_TOP; }
    __syncthreads();

    // 4 rounds, 8 bits each, MSB first
    for (int shift = 24; shift >= 0; shift -= 8) {
        if (tid < 256) hist[tid] = 0u;
        __syncthreads();
        unsigned prefix = s_prefix;
        unsigned himask = (shift == 24) ? 0u : (0xFFFFFFFFu << (shift + 8));
        for (int p = tid; p < HW; p += 1024) {
            unsigned u = f2key(st[p]);
            if ((u & himask) == prefix)
                atomicAdd(&hist[(u >> shift) & 255u], 1u);
        }
        __syncthreads();
        if (tid == 0) {
            unsigned rem = s_remaining;
            int b = 255;
            for (; b > 0; --b) {
                if (hist[b] >= rem) break;
                rem -= hist[b];
            }
            // b==0 fallthrough: remaining must land in bucket 0
            s_prefix    = prefix | ((unsigned)b << shift);
            s_remaining = rem;
        }
        __syncthreads();
    }

    const unsigned T = s_prefix;      // k-th largest key
    const unsigned r = s_remaining;   // number of ==T values to keep (lowest idx first)
    const float tau  = *tau_p;
    const float base = 1.0f - tau;

    // Count ==T in each thread's 16-element chunk, then exclusive block scan
    const int start = tid * 16;
    unsigned cnt = 0;
    #pragma unroll
    for (int i = 0; i < 16; ++i)
        cnt += (f2key(st[start + i]) == T) ? 1u : 0u;
    scnt[tid] = cnt;
    __syncthreads();

    // Kogge-Stone inclusive scan over 1024 entries
    for (int off = 1; off < 1024; off <<= 1) {
        unsigned v   = scnt[tid];
        unsigned add = (tid >= off) ? scnt[tid - off] : 0u;
        __syncthreads();
        scnt[tid] = v + add;
        __syncthreads();
    }
    unsigned excl = (tid == 0) ? 0u : scnt[tid - 1];

    // Emit fused factor
    #pragma unroll
    for (int i = 0; i < 16; ++i) {
        int p = start + i;
        unsigned u = f2key(st[p]);
        float m;
        if (u > T) {
            m = 1.0f;
        } else if (u == T) {
            m = (excl < r) ? 1.0f : 0.0f;
            excl += 1u;
        } else {
            m = 0.0f;
        }
        d_scale[n * HW + p] = m * tau + base;
    }
}

// ---------------------------------------------------------------------------
// Kernel C: out = x * scale[n][p], float4 throughout. scale (1 MiB) hits L2.
// ---------------------------------------------------------------------------
__global__ void apply_kernel(const float* __restrict__ x, float* __restrict__ out) {
    int j  = blockIdx.x * blockDim.x + threadIdx.x;   // float4 index, < 2^23
    int n  = j >> 19;                                  // per-sample f4 count = C_CH*HW4 = 2^19
    int p4 = j & (HW4 - 1);

    float4 s = reinterpret_cast<const float4*>(d_scale)[(n << 12) + p4];
    float4 a = reinterpret_cast<const float4*>(x)[j];
    float4 o;
    o.x = a.x * s.x; o.y = a.y * s.y; o.z = a.z * s.z; o.w = a.w * s.w;
    reinterpret_cast<float4*>(out)[j] = o;
}

// ---------------------------------------------------------------------------
extern "C" void kernel_launch(void* const* d_in, const int* in_sizes, int n_in,
                              void* d_out, int out_size) {
    const float* x   = (const float*)d_in[0];
    const float* tau = (const float*)d_in[1];
    float*       out = (float*)d_out;

    // A: N_S*HW4 = 65536 threads
    stats_kernel<<<(N_S * HW4) / 256, 256>>>(x);
    // B: one block per sample
    select_kernel<<<N_S, 1024>>>(tau);
    // C: N_S*C_CH*HW4 = 8388608 float4 threads
    apply_kernel<<<(N_S * C_CH * HW4) / 256, 256>>>(x, out);
}

// round 8
// speedup vs baseline: 1.0853x; 1.0853x over previous
#include <cuda_runtime.h>
#include <stdint.h>

// Problem constants: x [N, C, H, W] fp32
#define N_S   16
#define C_CH  128
#define HW    16384           // 128*128
#define HW4   4096            // HW / 4
#define K_TOP 1638            // max(int(0.1 * 16384), 1)

__device__ float d_stats[N_S * HW];   // per-(n, p) channel-sum
__device__ float d_scale[N_S * HW];   // per-(n, p) fused blend factor

// ---------------------------------------------------------------------------
// Kernel A: channel-sum per spatial column. One thread per float4 group of p.
// Software-pipelined: 16 loads batched per iteration, but the accumulation
// order into s0/s1 is IDENTICAL to the previous passing kernel (even channels
// -> s0, odd -> s1, in channel order). Bit-identical stats, higher MLP.
// ---------------------------------------------------------------------------
__global__ void __launch_bounds__(128) stats_kernel(const float* __restrict__ x) {
    int t  = blockIdx.x * 128 + threadIdx.x;          // [0, N_S*HW4)
    int n  = t >> 12;
    int p4 = t & (HW4 - 1);

    const float4* xp = reinterpret_cast<const float4*>(x) + ((size_t)n << 19) + p4;

    float4 s0 = make_float4(0.f, 0.f, 0.f, 0.f);
    float4 s1 = make_float4(0.f, 0.f, 0.f, 0.f);

    #pragma unroll
    for (int c = 0; c < C_CH; c += 16) {
        float4 v[16];
        #pragma unroll
        for (int k = 0; k < 16; ++k)
            v[k] = xp[(size_t)(c + k) << 12];
        #pragma unroll
        for (int k = 0; k < 16; k += 2) {
            s0.x += v[k].x;   s0.y += v[k].y;   s0.z += v[k].z;   s0.w += v[k].w;
            s1.x += v[k+1].x; s1.y += v[k+1].y; s1.z += v[k+1].z; s1.w += v[k+1].w;
        }
    }
    float4 s;
    s.x = s0.x + s1.x; s.y = s0.y + s1.y; s.z = s0.z + s1.z; s.w = s0.w + s1.w;
    reinterpret_cast<float4*>(d_stats)[t] = s;
}

// ---------------------------------------------------------------------------
// Kernel B: exact per-sample top-k via MSB-first radix select, fully
// register-resident (each thread holds 16 keys, lane-interleaved layout).
// Stable lowest-index tie-break via tie-count + (rare) binary search.
// One block per sample, 1024 threads.
// ---------------------------------------------------------------------------
__device__ __forceinline__ unsigned f2key(float f) {
    unsigned u = __float_as_uint(f);
    return u ^ ((unsigned)((int)u >> 31) | 0x80000000u);   // order-preserving
}

__device__ __forceinline__ unsigned block_reduce_add(unsigned v, unsigned* red) {
    #pragma unroll
    for (int o = 16; o; o >>= 1) v += __shfl_down_sync(0xFFFFFFFFu, v, o);
    int lane = threadIdx.x & 31, wid = threadIdx.x >> 5;
    if (lane == 0) red[wid] = v;
    __syncthreads();
    if (wid == 0) {
        unsigned r = red[lane];                    // 32 warps
        #pragma unroll
        for (int o = 16; o; o >>= 1) r += __shfl_down_sync(0xFFFFFFFFu, r, o);
        if (lane == 0) red[0] = r;
    }
    __syncthreads();
    unsigned r = red[0];
    __syncthreads();
    return r;
}

__global__ void __launch_bounds__(1024) select_kernel(const float* __restrict__ tau_p) {
    const int n   = blockIdx.x;
    const int tid = threadIdx.x;
    const float* st = d_stats + n * HW;

    unsigned key[16];
    #pragma unroll
    for (int i = 0; i < 16; ++i)
        key[i] = f2key(st[i * 1024 + tid]);        // coalesced

    __shared__ unsigned hist[256];
    __shared__ unsigned red[32];
    __shared__ unsigned s_prefix, s_rem;
    if (tid == 0) { s_prefix = 0u; s_rem = K_TOP; }
    __syncthreads();

    for (int shift = 24; shift >= 0; shift -= 8) {
        if (tid < 256) hist[tid] = 0u;
        __syncthreads();
        unsigned prefix = s_prefix;
        unsigned himask = (shift == 24) ? 0u : (0xFFFFFFFFu << (shift + 8));

        #pragma unroll
        for (int i = 0; i < 16; ++i) {
            unsigned u = key[i];
            bool act = ((u & himask) == prefix);
            unsigned bucket = act ? ((u >> shift) & 255u) : 0xFFFFFFFFu;
            unsigned m = __match_any_sync(0xFFFFFFFFu, bucket);  // warp-aggregate
            if (act && ((threadIdx.x & 31) == (unsigned)(__ffs(m) - 1)))
                atomicAdd(&hist[bucket], (unsigned)__popc(m));
        }
        __syncthreads();
        if (tid == 0) {
            unsigned rem = s_rem;
            int b = 255;
            for (; b > 0; --b) {
                if (hist[b] >= rem) break;
                rem -= hist[b];
            }
            s_prefix = prefix | ((unsigned)b << shift);
            s_rem    = rem;
        }
        __syncthreads();
    }

    const unsigned T = s_prefix;   // k-th largest key
    const unsigned r = s_rem;      // #ties to keep (lowest index first)

    // Tie resolution: keep ties with index <= M
    unsigned myT = 0;
    #pragma unroll
    for (int i = 0; i < 16; ++i) myT += (key[i] == T) ? 1u : 0u;
    unsigned cntT = block_reduce_add(myT, red);

    int M = HW - 1;
    if (cntT != r) {               // rare: more ties than slots
        int lo = 0, hi = HW - 1;
        while (lo < hi) {
            int mid = (lo + hi) >> 1;
            unsigned c = 0;
            #pragma unroll
            for (int i = 0; i < 16; ++i) {
                int p = i * 1024 + tid;
                c += (key[i] == T && p <= mid) ? 1u : 0u;
            }
            c = block_reduce_add(c, red);
            if (c >= r) hi = mid; else lo = mid + 1;
        }
        M = lo;
    }

    const float tau  = *tau_p;
    const float base = 1.0f - tau;
    #pragma unroll
    for (int i = 0; i < 16; ++i) {
        int p = i * 1024 + tid;
        unsigned u = key[i];
        float m = (u > T || (u == T && p <= M)) ? 1.0f : 0.0f;
        d_scale[n * HW + p] = m * tau + base;      // coalesced
    }
}

// ---------------------------------------------------------------------------
// Kernel C: out = x * scale[n][p]. 4 grid-strided float4 per thread with
// batched loads; scale (1 MiB) is L2-resident.
// ---------------------------------------------------------------------------
#define APPLY_TOT (N_S * C_CH * HW4 / 4)           // threads = 2097152

__global__ void __launch_bounds__(256) apply_kernel(const float* __restrict__ x,
                                                    float* __restrict__ out) {
    int t = blockIdx.x * 256 + threadIdx.x;
    const float4* xv = reinterpret_cast<const float4*>(x);
    const float4* sv = reinterpret_cast<const float4*>(d_scale);
    float4*       ov = reinterpret_cast<float4*>(out);

    int j0 = t;
    int j1 = t + APPLY_TOT;
    int j2 = t + 2 * APPLY_TOT;
    int j3 = t + 3 * APPLY_TOT;

    float4 a0 = xv[j0], a1 = xv[j1], a2 = xv[j2], a3 = xv[j3];
    float4 s0 = sv[((j0 >> 19) << 12) + (j0 & (HW4 - 1))];
    float4 s1 = sv[((j1 >> 19) << 12) + (j1 & (HW4 - 1))];
    float4 s2 = sv[((j2 >> 19) << 12) + (j2 & (HW4 - 1))];
    float4 s3 = sv[((j3 >> 19) << 12) + (j3 & (HW4 - 1))];

    float4 o;
    o.x = a0.x * s0.x; o.y = a0.y * s0.y; o.z = a0.z * s0.z; o.w = a0.w * s0.w; ov[j0] = o;
    o.x = a1.x * s1.x; o.y = a1.y * s1.y; o.z = a1.z * s1.z; o.w = a1.w * s1.w; ov[j1] = o;
    o.x = a2.x * s2.x; o.y = a2.y * s2.y; o.z = a2.z * s2.z; o.w = a2.w * s2.w; ov[j2] = o;
    o.x = a3.x * s3.x; o.y = a3.y * s3.y; o.z = a3.z * s3.z; o.w = a3.w * s3.w; ov[j3] = o;
}

// ---------------------------------------------------------------------------
extern "C" void kernel_launch(void* const* d_in, const int* in_sizes, int n_in,
                              void* d_out, int out_size) {
    const float* x   = (const float*)d_in[0];
    const float* tau = (const float*)d_in[1];
    float*       out = (float*)d_out;

    stats_kernel <<<(N_S * HW4) / 128, 128>>>(x);
    select_kernel<<<N_S, 1024>>>(tau);
    apply_kernel <<<APPLY_TOT / 256, 256>>>(x, out);
}

// round 11
// speedup vs baseline: 1.1086x; 1.0214x over previous
#include <cuda_runtime.h>
#include <stdint.h>

// Problem constants: x [N, C, H, W] fp32
#define N_S   16
#define C_CH  128
#define HW    16384           // 128*128
#define HW4   4096            // HW / 4
#define K_TOP 1638            // max(int(0.1 * 16384), 1)

__device__ float d_stats[N_S * HW];   // per-(n, p) channel-sum
__device__ float d_scale[N_S * HW];   // per-(n, p) fused blend factor

// ---------------------------------------------------------------------------
// Kernel A: channel-sum per spatial column, 2 threads per column (parity
// split). Thread with parity 0 sums even channels sequentially (== s0 of the
// previous passing kernel), parity 1 sums odd channels (== s1). Combined as
// s0 + s1 via smem -> bit-identical stats to the R8 passing kernel, but with
// 2x the warps in flight (131072 threads, ~28 warps/SM).
// ---------------------------------------------------------------------------
__global__ void __launch_bounds__(256) stats_kernel(const float* __restrict__ x) {
    const int tid    = threadIdx.x;
    const int colloc = tid & 127;                    // column within block
    const int parity = tid >> 7;                     // 0: evens, 1: odds
    const int col    = blockIdx.x * 128 + colloc;    // [0, N_S*HW4)
    const int n      = col >> 12;
    const int p4     = col & (HW4 - 1);

    // channel c = 2*k + parity, element offset = c*HW4
    const float4* xp = reinterpret_cast<const float4*>(x)
                     + ((size_t)n << 19) + ((size_t)parity << 12) + p4;

    float4 s = make_float4(0.f, 0.f, 0.f, 0.f);
    #pragma unroll
    for (int k0 = 0; k0 < 64; k0 += 8) {
        float4 v[8];
        #pragma unroll
        for (int i = 0; i < 8; ++i)
            v[i] = __ldcs(xp + ((size_t)(k0 + i) << 13));   // stride 2 channels
        #pragma unroll
        for (int i = 0; i < 8; ++i) {                        // sequential order
            s.x += v[i].x; s.y += v[i].y; s.z += v[i].z; s.w += v[i].w;
        }
    }

    __shared__ float4 sm[128];
    if (parity == 1) sm[colloc] = s;
    __syncthreads();
    if (parity == 0) {
        float4 s1 = sm[colloc];
        float4 t;                                            // s0 + s1, exact R8 order
        t.x = s.x + s1.x; t.y = s.y + s1.y; t.z = s.z + s1.z; t.w = s.w + s1.w;
        reinterpret_cast<float4*>(d_stats)[col] = t;
    }
}

// ---------------------------------------------------------------------------
// Kernel B: exact per-sample top-k via MSB-first radix select (register-
// resident keys, warp-aggregated histogram). Stable lowest-index tie-break.
// Writes fused blend factor  mask*tau + (1-tau). One block/sample.
// ---------------------------------------------------------------------------
__device__ __forceinline__ unsigned f2key(float f) {
    unsigned u = __float_as_uint(f);
    return u ^ ((unsigned)((int)u >> 31) | 0x80000000u);   // order-preserving
}

__device__ __forceinline__ unsigned block_reduce_add(unsigned v, unsigned* red) {
    #pragma unroll
    for (int o = 16; o; o >>= 1) v += __shfl_down_sync(0xFFFFFFFFu, v, o);
    int lane = threadIdx.x & 31, wid = threadIdx.x >> 5;
    if (lane == 0) red[wid] = v;
    __syncthreads();
    if (wid == 0) {
        unsigned r = red[lane];
        #pragma unroll
        for (int o = 16; o; o >>= 1) r += __shfl_down_sync(0xFFFFFFFFu, r, o);
        if (lane == 0) red[0] = r;
    }
    __syncthreads();
    unsigned r = red[0];
    __syncthreads();
    return r;
}

__global__ void __launch_bounds__(1024) select_kernel(const float* __restrict__ tau_p) {
    const int n   = blockIdx.x;
    const int tid = threadIdx.x;
    const float* st = d_stats + n * HW;

    unsigned key[16];
    #pragma unroll
    for (int i = 0; i < 16; ++i)
        key[i] = f2key(st[i * 1024 + tid]);        // coalesced

    __shared__ unsigned hist[256];
    __shared__ unsigned red[32];
    __shared__ unsigned s_prefix, s_rem;
    if (tid == 0) { s_prefix = 0u; s_rem = K_TOP; }
    __syncthreads();

    for (int shift = 24; shift >= 0; shift -= 8) {
        if (tid < 256) hist[tid] = 0u;
        __syncthreads();
        unsigned prefix = s_prefix;
        unsigned himask = (shift == 24) ? 0u : (0xFFFFFFFFu << (shift + 8));

        #pragma unroll
        for (int i = 0; i < 16; ++i) {
            unsigned u = key[i];
            bool act = ((u & himask) == prefix);
            unsigned bucket = act ? ((u >> shift) & 255u) : 0xFFFFFFFFu;
            unsigned m = __match_any_sync(0xFFFFFFFFu, bucket);
            if (act && ((threadIdx.x & 31) == (unsigned)(__ffs(m) - 1)))
                atomicAdd(&hist[bucket], (unsigned)__popc(m));
        }
        __syncthreads();
        if (tid == 0) {
            unsigned rem = s_rem;
            int b = 255;
            for (; b > 0; --b) {
                if (hist[b] >= rem) break;
                rem -= hist[b];
            }
            s_prefix = prefix | ((unsigned)b << shift);
            s_rem    = rem;
        }
        __syncthreads();
    }

    const unsigned T = s_prefix;   // k-th largest key
    const unsigned r = s_rem;      // #ties kept (lowest index first)

    unsigned myT = 0;
    #pragma unroll
    for (int i = 0; i < 16; ++i) myT += (key[i] == T) ? 1u : 0u;
    unsigned cntT = block_reduce_add(myT, red);

    int M = HW - 1;
    if (cntT != r) {               // rare: more ties than slots
        int lo = 0, hi = HW - 1;
        while (lo < hi) {
            int mid = (lo + hi) >> 1;
            unsigned c = 0;
            #pragma unroll
            for (int i = 0; i < 16; ++i) {
                int p = i * 1024 + tid;
                c += (key[i] == T && p <= mid) ? 1u : 0u;
            }
            c = block_reduce_add(c, red);
            if (c >= r) hi = mid; else lo = mid + 1;
        }
        M = lo;
    }

    const float tau  = *tau_p;
    const float base = 1.0f - tau;
    #pragma unroll
    for (int i = 0; i < 16; ++i) {
        int p = i * 1024 + tid;
        unsigned u = key[i];
        float m = (u > T || (u == T && p <= M)) ? 1.0f : 0.0f;
        d_scale[n * HW + p] = m * tau + base;
    }
}

// ---------------------------------------------------------------------------
// Kernel C: out = x * scale[n][p]. Each thread owns ONE spatial column and
// streams 32 channels: scale float4 loaded ONCE into registers (kills the
// 256 MiB L2 scale re-fetch), x via streaming loads, out via streaming
// stores. 262144 threads (~56 warps/SM), 8-deep batched loads.
// ---------------------------------------------------------------------------
__global__ void __launch_bounds__(256) apply_kernel(const float* __restrict__ x,
                                                    float* __restrict__ out) {
    const int t  = blockIdx.x * 256 + threadIdx.x;   // [0, 262144)
    const int p4 = t & (HW4 - 1);
    const int n  = (t >> 12) & 15;
    const int cq = t >> 16;                          // channel quarter: 0..3

    const float4 s = reinterpret_cast<const float4*>(d_scale)[(n << 12) + p4];

    const size_t base = ((size_t)((n << 7) + (cq << 5)) << 12) + p4;  // (n*128 + cq*32)*HW4 + p4
    const float4* xv = reinterpret_cast<const float4*>(x) + base;
    float4*       ov = reinterpret_cast<float4*>(out) + base;

    #pragma unroll
    for (int k0 = 0; k0 < 32; k0 += 8) {
        float4 v[8];
        #pragma unroll
        for (int i = 0; i < 8; ++i)
            v[i] = __ldcs(xv + ((size_t)(k0 + i) << 12));
        #pragma unroll
        for (int i = 0; i < 8; ++i) {
            float4 o;
            o.x = v[i].x * s.x; o.y = v[i].y * s.y;
            o.z = v[i].z * s.z; o.w = v[i].w * s.w;
            __stcs(ov + ((size_t)(k0 + i) << 12), o);
        }
    }
}

// ---------------------------------------------------------------------------
extern "C" void kernel_launch(void* const* d_in, const int* in_sizes, int n_in,
                              void* d_out, int out_size) {
    const float* x   = (const float*)d_in[0];
    const float* tau = (const float*)d_in[1];
    float*       out = (float*)d_out;

    stats_kernel <<<(N_S * HW4 * 2) / 256, 256>>>(x);   // 512 blocks
    select_kernel<<<N_S, 1024>>>(tau);
    apply_kernel <<<(N_S * HW4 * 4) / 256, 256>>>(x, out);  // 1024 blocks
}